// round 16
// baseline (speedup 1.0000x reference)
#include <cuda_runtime.h>
#include <cuda_fp16.h>

#define NN 50000
#define EE 800000
#define ET (EE + NN)
#define FD 128      // H*HID
#define EDD 16      // edge_dim
#define HIDD 32
#define HH 4
#define OUTD 64
#define NEGS 0.1f

typedef unsigned long long ull;

// ---------------- scratch (device globals) -----------------------------------
__device__ float  g_f0[NN * HIDD];
__device__ float  g_f1[NN * HIDD];
__device__ float  g_f2[NN * HIDD];
__device__ float  g_xl[(size_t)NN * FD];    // fp32 xl (alpha + aggregate gathers)
__device__ __half g_xrh[(size_t)NN * FD];   // fp16 xr (alpha gathers)
__device__ float  g_loop[NN * EDD];
__device__ float  g_cnt[NN];
__device__ float  g_ex[(size_t)ET * HH];
__device__ float  g_den[2][NN * HH];

__device__ __forceinline__ float lrelu(float v) { return fmaxf(v, NEGS * v); }

__device__ __forceinline__ void fma2(ull& acc, ull a, ull b) {
    asm("fma.rn.f32x2 %0, %1, %2, %0;" : "+l"(acc) : "l"(a), "l"(b));
}
__device__ __forceinline__ float2 upk(ull v) {
    float2 r; asm("mov.b64 {%0,%1}, %2;" : "=f"(r.x), "=f"(r.y) : "l"(v)); return r;
}
__device__ __forceinline__ ull pkh2(unsigned int h2) {
    float2 f = __half22float2(*(__half2*)&h2);
    ull r; asm("mov.b64 %0, {%1,%2};" : "=l"(r) : "f"(f.x), "f"(f.y)); return r;
}
__device__ __forceinline__ ull splat(float v) {
    ull r; asm("mov.b64 %0, {%1,%1};" : "=l"(r) : "f"(v)); return r;
}
__device__ __forceinline__ void red4(float* addr, float4 v) {
    asm volatile("red.global.add.v4.f32 [%0], {%1,%2,%3,%4};"
                 :: "l"(addr), "f"(v.x), "f"(v.y), "f"(v.z), "f"(v.w) : "memory");
}

// ------ launch 0: embed + zero loop/cnt/den + seed outputs with bias ---------
__global__ void k_embed_plus(const float* __restrict__ x, const float* __restrict__ W0,
                             const float* __restrict__ b0, const float* __restrict__ bng,
                             const float* __restrict__ bnb, const float* __restrict__ bnm,
                             const float* __restrict__ bnv,
                             const float* __restrict__ bias0, const float* __restrict__ bias1) {
    __shared__ float W0t[128 * 32];   // [k][j]
    int tid = threadIdx.x;
    for (int i = tid; i < 128 * 32; i += blockDim.x) {
        int k = i >> 5, j = i & 31;
        W0t[i] = W0[j * 128 + k];
    }
    __syncthreads();
    int warp = tid >> 5, lane = tid & 31;
    float sc = bng[lane] * rsqrtf(bnv[lane] + 1e-5f);
    float bb = bnb[lane], bm = bnm[lane], b00 = b0[lane];
#pragma unroll
    for (int it = 0; it < 8; it++) {
        int n = blockIdx.x * 64 + it * 8 + warp;
        if (n < NN) {
            const float4* xr4 = (const float4*)(x + (size_t)n * 128);
            float acc = 0.f;
#pragma unroll 8
            for (int kq = 0; kq < 32; kq++) {
                float4 v = xr4[kq];
                const float* wb = &W0t[(4 * kq) * 32 + lane];
                acc += v.x * wb[0] + v.y * wb[32] + v.z * wb[64] + v.w * wb[96];
            }
            acc += b00;
            acc = (acc - bm) * sc + bb;
            g_f0[n * 32 + lane] = lrelu(acc);
        }
    }
    // side work: zero accumulators (required for per-call idempotency)
    int gs = blockIdx.x * blockDim.x + tid;
    int stride = gridDim.x * blockDim.x;
    float4 z4 = make_float4(0.f, 0.f, 0.f, 0.f);
    for (int i = gs; i < NN * 4; i += stride) ((float4*)g_loop)[i] = z4;
    for (int i = gs; i < NN; i += stride) g_cnt[i] = 0.f;
    for (int i = gs; i < NN * HH; i += stride) { g_den[0][i] = 0.f; g_den[1][i] = 0.f; }
    for (int i = gs; i < NN * HIDD; i += stride) {
        g_f1[i] = bias0[i & 31];
        g_f2[i] = bias1[i & 31];
    }
}

// ------ launch 1: self-loop attr accumulation (vectorized reds) ---------------
__global__ void k_loop_accum(const int* __restrict__ ei, const float* __restrict__ ea) {
    int i = blockIdx.x * blockDim.x + threadIdx.x;
    if (i >= EE * 4) return;
    int e = i >> 2, q = i & 3;
    int dst = ei[EE + e];
    float4 v = ((const float4*)ea)[i];
    red4(&g_loop[dst * EDD + q * 4], v);
    if (q == 0) atomicAdd(&g_cnt[dst], 1.f);
}

// ------ node transforms -> fp32 xl, fp16 xr -------------------------------------
__global__ void k_xlxr(const float* __restrict__ feat,
                       const float* __restrict__ Wl, const float* __restrict__ bl,
                       const float* __restrict__ Wr, const float* __restrict__ br) {
    __shared__ float WlT[32 * 128];
    __shared__ float WrT[32 * 128];
    __shared__ float tile[32 * 32];
    int tid = threadIdx.x;
    for (int i = tid; i < 32 * 128; i += blockDim.x) {
        int k = i >> 7, j = i & 127;
        WlT[i] = Wl[j * 32 + k];
        WrT[i] = Wr[j * 32 + k];
    }
    int nbase = blockIdx.x * 32;
    for (int i = tid; i < 32 * 32; i += blockDim.x) {
        int n = nbase + (i >> 5);
        tile[i] = (n < NN) ? feat[n * 32 + (i & 31)] : 0.f;
    }
    __syncthreads();
    int j = tid & 127;
    int half = tid >> 7;
    float accl[16], accr[16];
#pragma unroll
    for (int n = 0; n < 16; n++) { accl[n] = 0.f; accr[n] = 0.f; }
#pragma unroll
    for (int k = 0; k < 32; k++) {
        float wl = WlT[k * 128 + j];
        float wr = WrT[k * 128 + j];
        const float* tr = &tile[(half * 16) * 32 + k];
#pragma unroll
        for (int n = 0; n < 16; n++) {
            float fv = tr[n * 32];
            accl[n] += fv * wl;
            accr[n] += fv * wr;
        }
    }
    float blj = bl[j], brj = br[j];
#pragma unroll
    for (int n = 0; n < 16; n++) {
        int node = nbase + half * 16 + n;
        if (node < NN) {
            g_xl[(size_t)node * 128 + j] = accl[n] + blj;
            g_xrh[(size_t)node * 128 + j] = __float2half(accr[n] + brj);
        }
    }
}

// ------ pass A: fp16 smem weights, float4 ev staging --------------------------
// lane owns channels 4*lane..4*lane+3 (head = lane>>3); warp does 8 edges; 8 tiles.
#define ALPHA_TILES 8
__global__ __launch_bounds__(256, 3)
void k_alpha(const int* __restrict__ ei, const float* __restrict__ eattr,
             const float* __restrict__ We, const float* __restrict__ att,
             float* __restrict__ den) {
    // WeH[dq][h][lane][k]: d = 4*dq + 2*h + (k>>2), ch = 4*lane + (k&3)
    __shared__ __half WeH[4][2][32][8];              // 4 KB
    __shared__ float4 evs[8][8][4];                  // [warp][edge][dquad] 8 KB
    int tid = threadIdx.x;
    for (int i = tid; i < 2048; i += blockDim.x) {
        int dq = i >> 9, h = (i >> 8) & 1, l = (i >> 3) & 31, k = i & 7;
        int d = 4 * dq + 2 * h + (k >> 2);
        int ch = 4 * l + (k & 3);
        ((__half*)WeH)[i] = __float2half(We[ch * 16 + d]);
    }
    __syncthreads();
    int warp = tid >> 5, lane = tid & 31;
    float4 att4 = ((const float4*)att)[lane];

    for (int t = 0; t < ALPHA_TILES; t++) {
        int e0 = (blockIdx.x * (8 * ALPHA_TILES) + t * 8 + warp) * 8;
        if (e0 >= ET) break;

        // edge indices: lanes 0-7 src, lanes 8-15 dst
        int sreg = 0, dreg = 0;
        {
            int le = e0 + (lane & 7);
            if (le < ET) {
                if (lane < 8)       sreg = (le < EE) ? ei[le]      : le - EE;
                else if (lane < 16) dreg = (le < EE) ? ei[EE + le] : le - EE;
            }
        }
        // stage eattr: lane -> edge = lane>>2, dims 4q..4q+3 (q = lane&3)
        {
            float4 ea4 = make_float4(0.f, 0.f, 0.f, 0.f);
            int ee = e0 + (lane >> 2);
            if (ee < EE) {
                ea4 = ((const float4*)eattr)[(size_t)ee * 4 + (lane & 3)];
            } else if (ee < ET) {
                int n = ee - EE;
                ea4 = ((const float4*)g_loop)[(size_t)n * 4 + (lane & 3)];
                float inv = 1.f / fmaxf(g_cnt[n], 1.f);
                ea4.x *= inv; ea4.y *= inv; ea4.z *= inv; ea4.w *= inv;
            }
            evs[warp][lane >> 2][lane & 3] = ea4;
        }
        __syncwarp();

        // EA accumulation: acc[e] packed as 2x f32x2
        ull acc01[8], acc23[8];
#pragma unroll
        for (int e = 0; e < 8; e++) { acc01[e] = 0ull; acc23[e] = 0ull; }
#pragma unroll
        for (int dq = 0; dq < 4; dq++) {
            uint4 wva = *(const uint4*)&WeH[dq][0][lane][0];   // d = 4dq, 4dq+1
            uint4 wvb = *(const uint4*)&WeH[dq][1][lane][0];   // d = 4dq+2, 4dq+3
            ull w0_01 = pkh2(wva.x), w0_23 = pkh2(wva.y);
            ull w1_01 = pkh2(wva.z), w1_23 = pkh2(wva.w);
            ull w2_01 = pkh2(wvb.x), w2_23 = pkh2(wvb.y);
            ull w3_01 = pkh2(wvb.z), w3_23 = pkh2(wvb.w);
#pragma unroll
            for (int e = 0; e < 8; e++) {
                float4 ev = evs[warp][e][dq];   // broadcast
                ull s0 = splat(ev.x), s1 = splat(ev.y), s2 = splat(ev.z), s3 = splat(ev.w);
                fma2(acc01[e], s0, w0_01); fma2(acc23[e], s0, w0_23);
                fma2(acc01[e], s1, w1_01); fma2(acc23[e], s1, w1_23);
                fma2(acc01[e], s2, w2_01); fma2(acc23[e], s2, w2_23);
                fma2(acc01[e], s3, w3_01); fma2(acc23[e], s3, w3_23);
            }
        }

#pragma unroll
        for (int e = 0; e < 8; e++) {
            int me = e0 + e;
            if (me >= ET) break;
            int se = __shfl_sync(0xffffffffu, sreg, e);
            int de = __shfl_sync(0xffffffffu, dreg, 8 + e);
            float4 xl4 = ((const float4*)(g_xl + (size_t)se * 128))[lane];
            uint2 xrh = ((const uint2*)(g_xrh + (size_t)de * 128))[lane];
            float2 xr01 = __half22float2(*(const __half2*)&xrh.x);
            float2 xr23 = __half22float2(*(const __half2*)&xrh.y);
            float2 a = upk(acc01[e]);
            float2 b = upk(acc23[e]);
            float t0 = lrelu(xl4.x + xr01.x + a.x) * att4.x;
            float t1 = lrelu(xl4.y + xr01.y + a.y) * att4.y;
            float t2 = lrelu(xl4.z + xr23.x + b.x) * att4.z;
            float t3 = lrelu(xl4.w + xr23.y + b.y) * att4.w;
            float s = (t0 + t1) + (t2 + t3);
            s += __shfl_xor_sync(0xffffffffu, s, 1);
            s += __shfl_xor_sync(0xffffffffu, s, 2);
            s += __shfl_xor_sync(0xffffffffu, s, 4);
            if ((lane & 7) == 0) {
                int h = lane >> 3;
                float ex = __expf(s);
                g_ex[(size_t)me * 4 + h] = ex;
                atomicAdd(&den[de * 4 + h], ex);
            }
        }
        __syncwarp();
    }
}

// ------ reciprocal of denominators (0.25 head-mean folded in) ------------------
__global__ void k_rcp(float* __restrict__ den) {
    int i = blockIdx.x * blockDim.x + threadIdx.x;
    if (i < NN * HH) den[i] = 0.25f / den[i];
}

// ------ pass C: weighted aggregate, batched gathers (MLP 8) --------------------
__global__ __launch_bounds__(256, 3)
void k_aggregate(const int* __restrict__ ei, const float* __restrict__ den,
                 float* __restrict__ outbuf) {
    int tid = threadIdx.x;
    int warp = tid >> 5, lane = tid & 31;
    for (int t = 0; t < 8; t++) {
        int e0 = (blockIdx.x * 64 + t * 8 + warp) * 8;
        if (e0 >= ET) break;
        int sreg = 0, dreg = 0;
        {
            int le = e0 + (lane & 7);
            if (le < ET) {
                if (lane < 8)       sreg = (le < EE) ? ei[le]      : le - EE;
                else if (lane < 16) dreg = (le < EE) ? ei[EE + le] : le - EE;
            }
        }
        int cnt = ET - e0; if (cnt > 8) cnt = 8;

        // ---- batch phase: issue all gathers (MLP up to 8) ----
        float4 xl[8];
        float w8[8];
#pragma unroll
        for (int e = 0; e < 8; e++) {
            if (e < cnt) {
                int se = __shfl_sync(0xffffffffu, sreg, e);
                xl[e] = __ldg((const float4*)(g_xl + (size_t)se * 128) + lane);
            }
        }
#pragma unroll
        for (int e = 0; e < 8; e++) {
            w8[e] = 0.f;
            if (e < cnt && lane < 4) {
                int de = __shfl_sync(0x0000000fu, dreg, 8 + e);   // note: dreg lives in lanes 8-15
                // need full-warp shfl for dreg (source lane 8+e)
            }
        }
        // (dreg broadcast needs full warp participation; do it in a separate pass)
#pragma unroll
        for (int e = 0; e < 8; e++) {
            int de = __shfl_sync(0xffffffffu, dreg, 8 + e);
            if (e < cnt && lane < 4)
                w8[e] = g_ex[(size_t)(e0 + e) * 4 + lane] * den[de * 4 + lane];  // den = 0.25/sum
        }

        // ---- reduce phase ----
#pragma unroll
        for (int e = 0; e < 8; e++) {
            if (e >= cnt) break;
            int de = __shfl_sync(0xffffffffu, dreg, 8 + e);
            float wl = __shfl_sync(0xffffffffu, w8[e], lane >> 3);
            float4 p;
            p.x = wl * xl[e].x; p.y = wl * xl[e].y; p.z = wl * xl[e].z; p.w = wl * xl[e].w;
            p.x += __shfl_xor_sync(0xffffffffu, p.x, 8);
            p.y += __shfl_xor_sync(0xffffffffu, p.y, 8);
            p.z += __shfl_xor_sync(0xffffffffu, p.z, 8);
            p.w += __shfl_xor_sync(0xffffffffu, p.w, 8);
            p.x += __shfl_xor_sync(0xffffffffu, p.x, 16);
            p.y += __shfl_xor_sync(0xffffffffu, p.y, 16);
            p.z += __shfl_xor_sync(0xffffffffu, p.z, 16);
            p.w += __shfl_xor_sync(0xffffffffu, p.w, 16);
            if (lane < 8) red4(&outbuf[de * 32 + 4 * lane], p);
        }
    }
}

// ------ output head (float4 feat loads) ------------------------------------------
__global__ void k_final(const float* __restrict__ feat, const float* __restrict__ Wout,
                        const float* __restrict__ bout, float* __restrict__ y) {
    __shared__ float WT[32 * 64];   // [c][o]
    int tid = threadIdx.x;
    for (int i = tid; i < 32 * 64; i += blockDim.x) {
        int c = i >> 6, o = i & 63;
        WT[i] = Wout[o * 32 + c];
    }
    __syncthreads();
    int o = tid & 63;
    float bo = bout[o];
#pragma unroll
    for (int it = 0; it < 16; it++) {
        int n = blockIdx.x * 64 + it * 4 + (tid >> 6);
        if (n >= NN) return;
        const float4* fr4 = (const float4*)(feat + n * 32);
        float acc = 0.f;
#pragma unroll
        for (int cq = 0; cq < 8; cq++) {
            float4 v = fr4[cq];
            const float* wb = &WT[(4 * cq) * 64 + o];
            acc += v.x * wb[0] + v.y * wb[64] + v.z * wb[128] + v.w * wb[192];
        }
        acc += bo;
        y[(size_t)n * 64 + o] = lrelu(acc);
    }
}

// =============================================================================
extern "C" void kernel_launch(void* const* d_in, const int* in_sizes, int n_in,
                              void* d_out, int out_size) {
    const float* x     = (const float*)d_in[0];
    const int*   ei    = (const int*)d_in[1];
    const float* eattr = (const float*)d_in[2];
    const float* W0    = (const float*)d_in[3];
    const float* b0    = (const float*)d_in[4];
    const float* bng   = (const float*)d_in[5];
    const float* bnb   = (const float*)d_in[6];
    const float* bnm   = (const float*)d_in[7];
    const float* bnv   = (const float*)d_in[8];
    const float* Wl[2]   = {(const float*)d_in[9],  (const float*)d_in[16]};
    const float* bl[2]   = {(const float*)d_in[10], (const float*)d_in[17]};
    const float* Wr[2]   = {(const float*)d_in[11], (const float*)d_in[18]};
    const float* br[2]   = {(const float*)d_in[12], (const float*)d_in[19]};
    const float* We[2]   = {(const float*)d_in[13], (const float*)d_in[20]};
    const float* att[2]  = {(const float*)d_in[14], (const float*)d_in[21]};
    const float* bias[2] = {(const float*)d_in[15], (const float*)d_in[22]};
    const float* Wout  = (const float*)d_in[23];
    const float* bout  = (const float*)d_in[24];
    float* y = (float*)d_out;

    float *f0, *f1, *f2, *den0, *den1;
    cudaGetSymbolAddress((void**)&f0, g_f0);
    cudaGetSymbolAddress((void**)&f1, g_f1);
    cudaGetSymbolAddress((void**)&f2, g_f2);
    cudaGetSymbolAddress((void**)&den0, g_den);
    den1 = den0 + NN * HH;

    k_embed_plus<<<(NN + 63) / 64, 256>>>(x, W0, b0, bng, bnb, bnm, bnv,
                                          bias[0], bias[1]);                         // 0
    k_loop_accum<<<(EE * 4 + 255) / 256, 256>>>(ei, eattr);                          // 1

    const float* fin[2]  = {f0, f1};
    float*       fden[2] = {den0, den1};
    float*       fout[2] = {f1, f2};
    int gedge = (ET + 511) / 512;   // 8 warps * 8 edges * 8 tiles per block
    for (int l = 0; l < 2; l++) {
        k_xlxr<<<(NN + 31) / 32, 256>>>(fin[l], Wl[l], bl[l], Wr[l], br[l]);         // 2, 6
        k_alpha<<<gedge, 256>>>(ei, eattr, We[l], att[l], fden[l]);                  // 3 <- profiled, 7
        k_rcp<<<(NN * HH + 255) / 256, 256>>>(fden[l]);                              // 4, 8
        k_aggregate<<<gedge, 256>>>(ei, fden[l], fout[l]);                           // 5, 9
    }
    k_final<<<(NN + 63) / 64, 256>>>(f2, Wout, bout, y);                             // 10
}

// round 17
// speedup vs baseline: 1.1185x; 1.1185x over previous
#include <cuda_runtime.h>
#include <cuda_fp16.h>

#define NN 50000
#define EE 800000
#define ET (EE + NN)
#define FD 128      // H*HID
#define EDD 16      // edge_dim
#define HIDD 32
#define HH 4
#define OUTD 64
#define NEGS 0.1f

typedef unsigned long long ull;

// ---------------- scratch (device globals) -----------------------------------
__device__ float  g_f0[NN * HIDD];
__device__ float  g_f1[NN * HIDD];
__device__ float  g_f2[NN * HIDD];
__device__ float  g_xl[(size_t)NN * FD];    // fp32 xl (alpha + aggregate gathers)
__device__ __half g_xrh[(size_t)NN * FD];   // fp16 xr (alpha gathers)
__device__ float  g_loop[NN * EDD];
__device__ float  g_cnt[NN];
__device__ float  g_ex[(size_t)ET * HH];
__device__ float  g_den[2][NN * HH];

__device__ __forceinline__ float lrelu(float v) { return fmaxf(v, NEGS * v); }

__device__ __forceinline__ void fma2(ull& acc, ull a, ull b) {
    asm("fma.rn.f32x2 %0, %1, %2, %0;" : "+l"(acc) : "l"(a), "l"(b));
}
__device__ __forceinline__ float2 upk(ull v) {
    float2 r; asm("mov.b64 {%0,%1}, %2;" : "=f"(r.x), "=f"(r.y) : "l"(v)); return r;
}
__device__ __forceinline__ ull pkh2(unsigned int h2) {
    float2 f = __half22float2(*(__half2*)&h2);
    ull r; asm("mov.b64 %0, {%1,%2};" : "=l"(r) : "f"(f.x), "f"(f.y)); return r;
}
__device__ __forceinline__ ull splat(float v) {
    ull r; asm("mov.b64 %0, {%1,%1};" : "=l"(r) : "f"(v)); return r;
}
__device__ __forceinline__ void red4(float* addr, float4 v) {
    asm volatile("red.global.add.v4.f32 [%0], {%1,%2,%3,%4};"
                 :: "l"(addr), "f"(v.x), "f"(v.y), "f"(v.z), "f"(v.w) : "memory");
}

// ------ launch 0: embed + zero loop/cnt/den + seed outputs with bias ---------
__global__ void k_embed_plus(const float* __restrict__ x, const float* __restrict__ W0,
                             const float* __restrict__ b0, const float* __restrict__ bng,
                             const float* __restrict__ bnb, const float* __restrict__ bnm,
                             const float* __restrict__ bnv,
                             const float* __restrict__ bias0, const float* __restrict__ bias1) {
    __shared__ float W0t[128 * 32];   // [k][j]
    int tid = threadIdx.x;
    for (int i = tid; i < 128 * 32; i += blockDim.x) {
        int k = i >> 5, j = i & 31;
        W0t[i] = W0[j * 128 + k];
    }
    __syncthreads();
    int warp = tid >> 5, lane = tid & 31;
    float sc = bng[lane] * rsqrtf(bnv[lane] + 1e-5f);
    float bb = bnb[lane], bm = bnm[lane], b00 = b0[lane];
#pragma unroll
    for (int it = 0; it < 8; it++) {
        int n = blockIdx.x * 64 + it * 8 + warp;
        if (n < NN) {
            const float4* xr4 = (const float4*)(x + (size_t)n * 128);
            float acc = 0.f;
#pragma unroll 8
            for (int kq = 0; kq < 32; kq++) {
                float4 v = xr4[kq];
                const float* wb = &W0t[(4 * kq) * 32 + lane];
                acc += v.x * wb[0] + v.y * wb[32] + v.z * wb[64] + v.w * wb[96];
            }
            acc += b00;
            acc = (acc - bm) * sc + bb;
            g_f0[n * 32 + lane] = lrelu(acc);
        }
    }
    // side work: zero accumulators (required for per-call idempotency)
    int gs = blockIdx.x * blockDim.x + tid;
    int stride = gridDim.x * blockDim.x;
    float4 z4 = make_float4(0.f, 0.f, 0.f, 0.f);
    for (int i = gs; i < NN * 4; i += stride) ((float4*)g_loop)[i] = z4;
    for (int i = gs; i < NN; i += stride) g_cnt[i] = 0.f;
    for (int i = gs; i < NN * HH; i += stride) { g_den[0][i] = 0.f; g_den[1][i] = 0.f; }
    for (int i = gs; i < NN * HIDD; i += stride) {
        g_f1[i] = bias0[i & 31];
        g_f2[i] = bias1[i & 31];
    }
}

// ------ launch 1: self-loop attr accumulation (vectorized reds) ---------------
__global__ void k_loop_accum(const int* __restrict__ ei, const float* __restrict__ ea) {
    int i = blockIdx.x * blockDim.x + threadIdx.x;
    if (i >= EE * 4) return;
    int e = i >> 2, q = i & 3;
    int dst = ei[EE + e];
    float4 v = ((const float4*)ea)[i];
    red4(&g_loop[dst * EDD + q * 4], v);
    if (q == 0) atomicAdd(&g_cnt[dst], 1.f);
}

// ------ node transforms -> fp32 xl, fp16 xr -------------------------------------
__global__ void k_xlxr(const float* __restrict__ feat,
                       const float* __restrict__ Wl, const float* __restrict__ bl,
                       const float* __restrict__ Wr, const float* __restrict__ br) {
    __shared__ float WlT[32 * 128];
    __shared__ float WrT[32 * 128];
    __shared__ float tile[32 * 32];
    int tid = threadIdx.x;
    for (int i = tid; i < 32 * 128; i += blockDim.x) {
        int k = i >> 7, j = i & 127;
        WlT[i] = Wl[j * 32 + k];
        WrT[i] = Wr[j * 32 + k];
    }
    int nbase = blockIdx.x * 32;
    for (int i = tid; i < 32 * 32; i += blockDim.x) {
        int n = nbase + (i >> 5);
        tile[i] = (n < NN) ? feat[n * 32 + (i & 31)] : 0.f;
    }
    __syncthreads();
    int j = tid & 127;
    int half = tid >> 7;
    float accl[16], accr[16];
#pragma unroll
    for (int n = 0; n < 16; n++) { accl[n] = 0.f; accr[n] = 0.f; }
#pragma unroll
    for (int k = 0; k < 32; k++) {
        float wl = WlT[k * 128 + j];
        float wr = WrT[k * 128 + j];
        const float* tr = &tile[(half * 16) * 32 + k];
#pragma unroll
        for (int n = 0; n < 16; n++) {
            float fv = tr[n * 32];
            accl[n] += fv * wl;
            accr[n] += fv * wr;
        }
    }
    float blj = bl[j], brj = br[j];
#pragma unroll
    for (int n = 0; n < 16; n++) {
        int node = nbase + half * 16 + n;
        if (node < NN) {
            g_xl[(size_t)node * 128 + j] = accl[n] + blj;
            g_xrh[(size_t)node * 128 + j] = __float2half(accr[n] + brj);
        }
    }
}

// ------ pass A: fp16 smem weights, float4 ev staging --------------------------
// lane owns channels 4*lane..4*lane+3 (head = lane>>3); warp does 8 edges; 8 tiles.
#define ALPHA_TILES 8
__global__ __launch_bounds__(256, 3)
void k_alpha(const int* __restrict__ ei, const float* __restrict__ eattr,
             const float* __restrict__ We, const float* __restrict__ att,
             float* __restrict__ den) {
    // WeH[dq][h][lane][k]: d = 4*dq + 2*h + (k>>2), ch = 4*lane + (k&3)
    __shared__ __half WeH[4][2][32][8];              // 4 KB
    __shared__ float4 evs[8][8][4];                  // [warp][edge][dquad] 8 KB
    int tid = threadIdx.x;
    for (int i = tid; i < 2048; i += blockDim.x) {
        int dq = i >> 9, h = (i >> 8) & 1, l = (i >> 3) & 31, k = i & 7;
        int d = 4 * dq + 2 * h + (k >> 2);
        int ch = 4 * l + (k & 3);
        ((__half*)WeH)[i] = __float2half(We[ch * 16 + d]);
    }
    __syncthreads();
    int warp = tid >> 5, lane = tid & 31;
    float4 att4 = ((const float4*)att)[lane];

    for (int t = 0; t < ALPHA_TILES; t++) {
        int e0 = (blockIdx.x * (8 * ALPHA_TILES) + t * 8 + warp) * 8;
        if (e0 >= ET) break;

        // edge indices: lanes 0-7 src, lanes 8-15 dst
        int sreg = 0, dreg = 0;
        {
            int le = e0 + (lane & 7);
            if (le < ET) {
                if (lane < 8)       sreg = (le < EE) ? ei[le]      : le - EE;
                else if (lane < 16) dreg = (le < EE) ? ei[EE + le] : le - EE;
            }
        }
        // stage eattr: lane -> edge = lane>>2, dims 4q..4q+3 (q = lane&3)
        {
            float4 ea4 = make_float4(0.f, 0.f, 0.f, 0.f);
            int ee = e0 + (lane >> 2);
            if (ee < EE) {
                ea4 = ((const float4*)eattr)[(size_t)ee * 4 + (lane & 3)];
            } else if (ee < ET) {
                int n = ee - EE;
                ea4 = ((const float4*)g_loop)[(size_t)n * 4 + (lane & 3)];
                float inv = 1.f / fmaxf(g_cnt[n], 1.f);
                ea4.x *= inv; ea4.y *= inv; ea4.z *= inv; ea4.w *= inv;
            }
            evs[warp][lane >> 2][lane & 3] = ea4;
        }
        __syncwarp();

        // EA accumulation: acc[e] packed as 2x f32x2
        ull acc01[8], acc23[8];
#pragma unroll
        for (int e = 0; e < 8; e++) { acc01[e] = 0ull; acc23[e] = 0ull; }
#pragma unroll
        for (int dq = 0; dq < 4; dq++) {
            uint4 wva = *(const uint4*)&WeH[dq][0][lane][0];   // d = 4dq, 4dq+1
            uint4 wvb = *(const uint4*)&WeH[dq][1][lane][0];   // d = 4dq+2, 4dq+3
            ull w0_01 = pkh2(wva.x), w0_23 = pkh2(wva.y);
            ull w1_01 = pkh2(wva.z), w1_23 = pkh2(wva.w);
            ull w2_01 = pkh2(wvb.x), w2_23 = pkh2(wvb.y);
            ull w3_01 = pkh2(wvb.z), w3_23 = pkh2(wvb.w);
#pragma unroll
            for (int e = 0; e < 8; e++) {
                float4 ev = evs[warp][e][dq];   // broadcast
                ull s0 = splat(ev.x), s1 = splat(ev.y), s2 = splat(ev.z), s3 = splat(ev.w);
                fma2(acc01[e], s0, w0_01); fma2(acc23[e], s0, w0_23);
                fma2(acc01[e], s1, w1_01); fma2(acc23[e], s1, w1_23);
                fma2(acc01[e], s2, w2_01); fma2(acc23[e], s2, w2_23);
                fma2(acc01[e], s3, w3_01); fma2(acc23[e], s3, w3_23);
            }
        }

#pragma unroll
        for (int e = 0; e < 8; e++) {
            int me = e0 + e;
            if (me >= ET) break;
            int se = __shfl_sync(0xffffffffu, sreg, e);
            int de = __shfl_sync(0xffffffffu, dreg, 8 + e);
            float4 xl4 = ((const float4*)(g_xl + (size_t)se * 128))[lane];
            uint2 xrh = ((const uint2*)(g_xrh + (size_t)de * 128))[lane];
            float2 xr01 = __half22float2(*(const __half2*)&xrh.x);
            float2 xr23 = __half22float2(*(const __half2*)&xrh.y);
            float2 a = upk(acc01[e]);
            float2 b = upk(acc23[e]);
            float t0 = lrelu(xl4.x + xr01.x + a.x) * att4.x;
            float t1 = lrelu(xl4.y + xr01.y + a.y) * att4.y;
            float t2 = lrelu(xl4.z + xr23.x + b.x) * att4.z;
            float t3 = lrelu(xl4.w + xr23.y + b.y) * att4.w;
            float s = (t0 + t1) + (t2 + t3);
            s += __shfl_xor_sync(0xffffffffu, s, 1);
            s += __shfl_xor_sync(0xffffffffu, s, 2);
            s += __shfl_xor_sync(0xffffffffu, s, 4);
            if ((lane & 7) == 0) {
                int h = lane >> 3;
                float ex = __expf(s);
                g_ex[(size_t)me * 4 + h] = ex;
                atomicAdd(&den[de * 4 + h], ex);
            }
        }
        __syncwarp();
    }
}

// ------ reciprocal of denominators (0.25 head-mean folded in) ------------------
__global__ void k_rcp(float* __restrict__ den) {
    int i = blockIdx.x * blockDim.x + threadIdx.x;
    if (i < NN * HH) den[i] = 0.25f / den[i];
}

// ------ pass C: weighted aggregate, depth-2 pipelined gathers -------------------
__global__ void k_aggregate(const int* __restrict__ ei, const float* __restrict__ den,
                            float* __restrict__ outbuf) {
    int tid = threadIdx.x;
    int warp = tid >> 5, lane = tid & 31;
    for (int t = 0; t < 8; t++) {
        int e0 = (blockIdx.x * 64 + t * 8 + warp) * 8;
        if (e0 >= ET) break;
        int sreg = 0, dreg = 0;
        {
            int le = e0 + (lane & 7);
            if (le < ET) {
                if (lane < 8)       sreg = (le < EE) ? ei[le]      : le - EE;
                else if (lane < 16) dreg = (le < EE) ? ei[EE + le] : le - EE;
            }
        }
        int cnt = ET - e0; if (cnt > 8) cnt = 8;

        // prologue: issue edge 0's gathers
        int se0 = __shfl_sync(0xffffffffu, sreg, 0);
        int de_cur = __shfl_sync(0xffffffffu, dreg, 8);
        float4 xl_cur = __ldg((const float4*)(g_xl + (size_t)se0 * 128) + lane);
        float w_cur = 0.f;
        if (lane < 4) w_cur = g_ex[(size_t)e0 * 4 + lane] * den[de_cur * 4 + lane];

#pragma unroll
        for (int e = 0; e < 8; e++) {
            if (e >= cnt) break;
            // prefetch edge e+1 (overlaps with reduce of edge e)
            float4 xl_nxt = xl_cur;
            float w_nxt = 0.f;
            int de_nxt = de_cur;
            if (e + 1 < cnt) {
                int se_n = __shfl_sync(0xffffffffu, sreg, e + 1);
                de_nxt = __shfl_sync(0xffffffffu, dreg, 8 + e + 1);
                xl_nxt = __ldg((const float4*)(g_xl + (size_t)se_n * 128) + lane);
                if (lane < 4)
                    w_nxt = g_ex[(size_t)(e0 + e + 1) * 4 + lane] * den[de_nxt * 4 + lane];
            }
            // reduce edge e
            float wl = __shfl_sync(0xffffffffu, w_cur, lane >> 3);
            float4 p;
            p.x = wl * xl_cur.x; p.y = wl * xl_cur.y; p.z = wl * xl_cur.z; p.w = wl * xl_cur.w;
            p.x += __shfl_xor_sync(0xffffffffu, p.x, 8);
            p.y += __shfl_xor_sync(0xffffffffu, p.y, 8);
            p.z += __shfl_xor_sync(0xffffffffu, p.z, 8);
            p.w += __shfl_xor_sync(0xffffffffu, p.w, 8);
            p.x += __shfl_xor_sync(0xffffffffu, p.x, 16);
            p.y += __shfl_xor_sync(0xffffffffu, p.y, 16);
            p.z += __shfl_xor_sync(0xffffffffu, p.z, 16);
            p.w += __shfl_xor_sync(0xffffffffu, p.w, 16);
            if (lane < 8) red4(&outbuf[de_cur * 32 + 4 * lane], p);
            xl_cur = xl_nxt; w_cur = w_nxt; de_cur = de_nxt;
        }
    }
}

// ------ output head (float4 feat loads) ------------------------------------------
__global__ void k_final(const float* __restrict__ feat, const float* __restrict__ Wout,
                        const float* __restrict__ bout, float* __restrict__ y) {
    __shared__ float WT[32 * 64];   // [c][o]
    int tid = threadIdx.x;
    for (int i = tid; i < 32 * 64; i += blockDim.x) {
        int c = i >> 6, o = i & 63;
        WT[i] = Wout[o * 32 + c];
    }
    __syncthreads();
    int o = tid & 63;
    float bo = bout[o];
#pragma unroll
    for (int it = 0; it < 16; it++) {
        int n = blockIdx.x * 64 + it * 4 + (tid >> 6);
        if (n >= NN) return;
        const float4* fr4 = (const float4*)(feat + n * 32);
        float acc = 0.f;
#pragma unroll
        for (int cq = 0; cq < 8; cq++) {
            float4 v = fr4[cq];
            const float* wb = &WT[(4 * cq) * 64 + o];
            acc += v.x * wb[0] + v.y * wb[64] + v.z * wb[128] + v.w * wb[192];
        }
        acc += bo;
        y[(size_t)n * 64 + o] = lrelu(acc);
    }
}

// =============================================================================
extern "C" void kernel_launch(void* const* d_in, const int* in_sizes, int n_in,
                              void* d_out, int out_size) {
    const float* x     = (const float*)d_in[0];
    const int*   ei    = (const int*)d_in[1];
    const float* eattr = (const float*)d_in[2];
    const float* W0    = (const float*)d_in[3];
    const float* b0    = (const float*)d_in[4];
    const float* bng   = (const float*)d_in[5];
    const float* bnb   = (const float*)d_in[6];
    const float* bnm   = (const float*)d_in[7];
    const float* bnv   = (const float*)d_in[8];
    const float* Wl[2]   = {(const float*)d_in[9],  (const float*)d_in[16]};
    const float* bl[2]   = {(const float*)d_in[10], (const float*)d_in[17]};
    const float* Wr[2]   = {(const float*)d_in[11], (const float*)d_in[18]};
    const float* br[2]   = {(const float*)d_in[12], (const float*)d_in[19]};
    const float* We[2]   = {(const float*)d_in[13], (const float*)d_in[20]};
    const float* att[2]  = {(const float*)d_in[14], (const float*)d_in[21]};
    const float* bias[2] = {(const float*)d_in[15], (const float*)d_in[22]};
    const float* Wout  = (const float*)d_in[23];
    const float* bout  = (const float*)d_in[24];
    float* y = (float*)d_out;

    float *f0, *f1, *f2, *den0, *den1;
    cudaGetSymbolAddress((void**)&f0, g_f0);
    cudaGetSymbolAddress((void**)&f1, g_f1);
    cudaGetSymbolAddress((void**)&f2, g_f2);
    cudaGetSymbolAddress((void**)&den0, g_den);
    den1 = den0 + NN * HH;

    k_embed_plus<<<(NN + 63) / 64, 256>>>(x, W0, b0, bng, bnb, bnm, bnv,
                                          bias[0], bias[1]);                         // 0
    k_loop_accum<<<(EE * 4 + 255) / 256, 256>>>(ei, eattr);                          // 1

    const float* fin[2]  = {f0, f1};
    float*       fden[2] = {den0, den1};
    float*       fout[2] = {f1, f2};
    int gedge = (ET + 511) / 512;   // 8 warps * 8 edges * 8 tiles per block
    for (int l = 0; l < 2; l++) {
        k_xlxr<<<(NN + 31) / 32, 256>>>(fin[l], Wl[l], bl[l], Wr[l], br[l]);         // 2, 6
        k_alpha<<<gedge, 256>>>(ei, eattr, We[l], att[l], fden[l]);                  // 3 <- profiled, 7
        k_rcp<<<(NN * HH + 255) / 256, 256>>>(fden[l]);                              // 4, 8
        k_aggregate<<<gedge, 256>>>(ei, fden[l], fout[l]);                           // 5, 9
    }
    k_final<<<(NN + 63) / 64, 256>>>(f2, Wout, bout, y);                             // 10
}